// round 17
// baseline (speedup 1.0000x reference)
#include <cuda_runtime.h>
#include <cuda_fp16.h>
#include <cstdint>

// ---------------- problem constants ----------------
#define BATCH 2
#define S_LEN 512
#define HID 2048
#define NHEAD 32
#define HDIM 64
#define SU_LEN 1024
#define T_LEN 1536
#define INTER 5632
#define EPS_RMS 1e-6f

#define S_H   (S_LEN * HID)
#define SU_H  (SU_LEN * HID)
#define T_H   (T_LEN * HID)
#define SU_I  ((long long)SU_LEN * INTER)

#define HB  (BATCH * S_LEN * HID)
#define XB  (BATCH * SU_LEN * HID)
#define KBN (BATCH * T_LEN * HID)
#define UBB ((long long)BATCH * SU_LEN * INTER)
#define WUPN (SU_LEN * S_LEN)
#define W1N  (HID * HID)
#define W2N  (INTER * HID)

typedef __half hf;

// ---------------- scratch (device globals; no runtime allocation) ----------------
__device__ float g_up  [XB];
__device__ float g_x1  [XB];
__device__ float g_x2  [XB];
__device__ float g_x3  [XB];

__device__ hf f_c  [BATCH * T_LEN * HID];   // combined [h; up] fp16, per batch
__device__ hf f_ht [HB];
__device__ hf f_wup[WUPN];
__device__ hf f_wqkv[3 * W1N];              // [Wq; Wk; Wv] rows
__device__ hf f_wo[W1N];
__device__ hf f_wg[W2N];
__device__ hf f_wu[W2N];
__device__ hf f_wd[W2N];
__device__ hf f_x1 [XB];
__device__ hf f_x3 [XB];
__device__ hf f_q  [XB];
__device__ hf f_k  [KBN];
__device__ hf f_v  [KBN];
__device__ hf f_o  [XB];
__device__ hf f_gate[UBB];
__device__ hf f_ub [UBB];

// ---------------- PTX helpers ----------------
__device__ __forceinline__ uint32_t smem_u32(const void* p) {
    uint32_t a;
    asm("{ .reg .u64 t; cvta.to.shared.u64 t, %1; cvt.u32.u64 %0, t; }" : "=r"(a) : "l"(p));
    return a;
}
#define SWZ(off) ((off) ^ (((off) >> 3) & 0x70))

#define CP_ASYNC16(dst, src) \
    asm volatile("cp.async.cg.shared.global [%0], [%1], 16;" :: "r"(dst), "l"(src) : "memory")
#define CP_COMMIT() asm volatile("cp.async.commit_group;" ::: "memory")
__device__ __forceinline__ void cp_wait(int allow) {
    if (allow) asm volatile("cp.async.wait_group 1;" ::: "memory");
    else       asm volatile("cp.async.wait_group 0;" ::: "memory");
}

__device__ __forceinline__ void ldmx4(uint32_t* r, uint32_t addr) {
    asm volatile("ldmatrix.sync.aligned.m8n8.x4.shared.b16 {%0,%1,%2,%3}, [%4];"
        : "=r"(r[0]), "=r"(r[1]), "=r"(r[2]), "=r"(r[3]) : "r"(addr));
}
__device__ __forceinline__ void ldmx4t(uint32_t* r, uint32_t addr) {
    asm volatile("ldmatrix.sync.aligned.m8n8.x4.trans.shared.b16 {%0,%1,%2,%3}, [%4];"
        : "=r"(r[0]), "=r"(r[1]), "=r"(r[2]), "=r"(r[3]) : "r"(addr));
}

__device__ __forceinline__ void mma_f16(float* d, const uint32_t* a, uint32_t b0, uint32_t b1) {
    asm volatile("mma.sync.aligned.m16n8k16.row.col.f32.f16.f16.f32 "
        "{%0,%1,%2,%3}, {%4,%5,%6,%7}, {%8,%9}, {%0,%1,%2,%3};"
        : "+f"(d[0]), "+f"(d[1]), "+f"(d[2]), "+f"(d[3])
        : "r"(a[0]), "r"(a[1]), "r"(a[2]), "r"(a[3]), "r"(b0), "r"(b1));
}

__device__ __forceinline__ uint32_t pack_f16x2(hf a, hf b) {
    __half2 t;
    t.x = a; t.y = b;
    return *(uint32_t*)&t;
}

// ---------------- mma.sync GEMM (pure fp16, fp32 accumulate) ----------------
// 128 threads, 4 warps in 2x2, warp tile 64x64, CTA tile 128x128, BK=64, 3 stages.
// A-fragments software-pipelined across ks; B-fragments across ng.
__global__ __launch_bounds__(128, 2) void mma_gemm(
    const hf* __restrict__ A0, int lda, long long sA1,
    const hf* __restrict__ B0, int ldb, long long sB1,
    float* __restrict__ C, hf* __restrict__ Chi, int ldc, long long sC1,
    const float* __restrict__ bias,
    const float* __restrict__ resid, int ldr, long long sR1,
    const hf* __restrict__ gate,
    hf* __restrict__ s0, long long ss0,
    hf* __restrict__ s1, long long ss1,
    int K, float alpha)
{
    extern __shared__ char smem[];
    const uint32_t sbase = smem_u32(smem);
    const uint32_t tiles = (sbase + 1023u) & ~1023u;
    constexpr int ASZ = 128 * 128;
    constexpr int STG = 2 * ASZ;       // 32 KB per stage

    const int tid = threadIdx.x, wid = tid >> 5, lane = tid & 31;
    const int z = blockIdx.z;
    const hf* A = A0 + (long long)z * sA1;
    const hf* B = B0 + (long long)z * sB1;
    const int m0 = blockIdx.y * 128, n0 = blockIdx.x * 128;
    const int m0w = (wid & 1) * 64;
    const int n0w = (wid >> 1) * 64;

    const int nc = K >> 6;

    // ---- strength-reduced loader state ----
    const int tr = tid >> 3, tg = tid & 7;
    const uint32_t lsOff = (uint32_t)(tr * 128 + ((tg * 16) ^ ((tr & 7) * 16)));
    const hf* aCur = A + (long long)(m0 + tr) * lda + tg * 8;
    const hf* bCur = B + (long long)(n0 + tr) * ldb + tg * 8;
    const long long aStep = 16LL * lda;
    const long long bStep = 16LL * ldb;

    auto load_chunk = [&](int s) {
        const uint32_t aB = tiles + s * STG + lsOff;
        const uint32_t bB = aB + ASZ;
        const hf* p = aCur;
        #pragma unroll
        for (int sl = 0; sl < 8; sl++) { CP_ASYNC16(aB + sl * 2048, p); p += aStep; }
        p = bCur;
        #pragma unroll
        for (int sl = 0; sl < 8; sl++) { CP_ASYNC16(bB + sl * 2048, p); p += bStep; }
        CP_COMMIT();
        aCur += 64; bCur += 64;
    };

    float acc[4][8][4];
    #pragma unroll
    for (int i = 0; i < 4; i++)
        #pragma unroll
        for (int j = 0; j < 8; j++)
            #pragma unroll
            for (int q = 0; q < 4; q++) acc[i][j][q] = 0.f;

    load_chunk(0);
    if (nc > 1) load_chunk(1);

    const int lrow = lane & 15;
    const int lcol = (lane >> 4) * 16;

    for (int c = 0; c < nc; c++) {
        const int s = c % 3;
        cp_wait(c + 1 < nc ? 1 : 0);
        __syncthreads();
        if (c + 2 < nc) load_chunk((c + 2) % 3);

        const uint32_t aSt = tiles + s * STG;
        const uint32_t bSt = aSt + ASZ;

        // preload A-frags for ks=0
        uint32_t ra[2][4][4];
        #pragma unroll
        for (int mt = 0; mt < 4; mt++)
            ldmx4(ra[0][mt], aSt + SWZ((m0w + mt * 16 + lrow) * 128 + lcol));

        #pragma unroll
        for (int ks = 0; ks < 4; ks++) {
            const int cur = ks & 1, nxt = cur ^ 1;
            uint32_t rb[2][4];
            ldmx4(rb[0], bSt + SWZ((n0w + lrow) * 128 + ks * 32 + lcol));
            if (ks < 3)
                #pragma unroll
                for (int mt = 0; mt < 4; mt++)
                    ldmx4(ra[nxt][mt],
                          aSt + SWZ((m0w + mt * 16 + lrow) * 128 + (ks + 1) * 32 + lcol));
            #pragma unroll
            for (int ng = 0; ng < 4; ng++) {
                if (ng < 3)
                    ldmx4(rb[(ng + 1) & 1],
                          bSt + SWZ((n0w + (ng + 1) * 16 + lrow) * 128 + ks * 32 + lcol));
                const uint32_t* rbc = rb[ng & 1];
                #pragma unroll
                for (int mt = 0; mt < 4; mt++) {
                    mma_f16(acc[mt][2 * ng],     ra[cur][mt], rbc[0], rbc[2]);
                    mma_f16(acc[mt][2 * ng + 1], ra[cur][mt], rbc[1], rbc[3]);
                }
            }
        }
        __syncthreads();
    }

    // ---- epilogue ----
    hf* hOut;
    long long hAdj;
    if (s0) {
        const int seg = n0 >> 11;
        hOut = seg ? s1 : s0;
        hAdj = (long long)z * (seg ? ss1 : ss0) - ((long long)seg << 11);
    } else {
        hOut = Chi;
        hAdj = (long long)z * sC1;
    }
    float* fOut = C;
    const long long fAdj = (long long)z * sC1;

    const int rq = lane >> 2;
    const int cq = (lane & 3) * 2;
    #pragma unroll
    for (int mt = 0; mt < 4; mt++) {
        #pragma unroll
        for (int half = 0; half < 2; half++) {
            const int m = m0 + m0w + mt * 16 + rq + half * 8;
            const float bv = bias ? bias[m] : 0.f;
            const long long hBase = hAdj + (long long)m * ldc + n0 + n0w;
            const long long fBase = fAdj + (long long)m * ldc + n0 + n0w;
            const long long rBase = resid ? ((long long)z * sR1 +
                                             (long long)m * ldr + n0 + n0w) : 0;
            #pragma unroll
            for (int nt = 0; nt < 8; nt++) {
                float v0 = acc[mt][nt][half * 2]     * alpha + bv;
                float v1 = acc[mt][nt][half * 2 + 1] * alpha + bv;
                const int cn = nt * 8 + cq;
                if (resid) {
                    v0 += resid[rBase + cn];
                    v1 += resid[rBase + cn + 1];
                }
                if (gate) {
                    __half2 gp = *(const __half2*)(gate + hBase + cn);
                    float g0 = __half2float(gp.x), g1 = __half2float(gp.y);
                    v0 *= g0 / (1.f + __expf(-g0));
                    v1 *= g1 / (1.f + __expf(-g1));
                }
                if (fOut)
                    *(float2*)(fOut + fBase + cn) = make_float2(v0, v1);
                if (hOut)
                    *(uint32_t*)(hOut + hBase + cn) =
                        pack_f16x2(__float2half(v0), __float2half(v1));
            }
        }
    }
}

// ---------------- fused flash attention (pure fp16, V in [t,d] layout) ----------------
#define FA_NI (T_LEN / 128)   // 12

__global__ __launch_bounds__(256, 1) void flash_attn(
    const hf* __restrict__ gq,
    const hf* __restrict__ gk,
    const hf* __restrict__ gv,
    hf* __restrict__ go)
{
    extern __shared__ char smem[];
    const uint32_t sb0 = smem_u32(smem);
    const uint32_t sb = (sb0 + 1023u) & ~1023u;
    const uint32_t Q = sb;
    const uint32_t ST0 = sb + 16384;
    const uint32_t STSZ = 32768;

    const int tid = threadIdx.x, wid = tid >> 5, lane = tid & 31;
    const int q0 = blockIdx.x * 128;
    const int bh = blockIdx.y;
    const int b = bh >> 5, head = bh & 31;

    const hf* qp = gq + (long long)b * SU_H + head * HDIM;
    const hf* kp = gk + (long long)b * T_H + head * HDIM;
    const hf* vp = gv + (long long)b * T_H + head * HDIM;

    for (int u = tid; u < 1024; u += 256) {
        int r = u >> 3, g = u & 7;
        CP_ASYNC16(Q + SWZ(r * 128 + g * 16), qp + (long long)(q0 + r) * HID + g * 8);
    }
    CP_COMMIT();

    const int tr = tid >> 3, tg = tid & 7;
    const uint32_t lsOff = (uint32_t)(tr * 128 + ((tg * 16) ^ ((tr & 7) * 16)));
    const hf* kCur = kp + (long long)tr * HID + tg * 8;
    const hf* vCur = vp + (long long)tr * HID + tg * 8;
    const long long rStep = 32LL * HID;

    auto loadkv = [&](int s) {
        const uint32_t kB = ST0 + s * STSZ + lsOff;
        const uint32_t vB = kB + 16384;
        const hf* p = kCur;
        #pragma unroll
        for (int sl = 0; sl < 4; sl++) { CP_ASYNC16(kB + sl * 4096, p); p += rStep; }
        p = vCur;
        #pragma unroll
        for (int sl = 0; sl < 4; sl++) { CP_ASYNC16(vB + sl * 4096, p); p += rStep; }
        CP_COMMIT();
        kCur += 128LL * HID; vCur += 128LL * HID;
    };

    loadkv(0);
    loadkv(1);
    cp_wait(1);
    __syncthreads();

    const int lrow = lane & 15, lcol = (lane >> 4) * 16;
    const int mrow = wid * 16;
    uint32_t qf[4][4];
    #pragma unroll
    for (int ks = 0; ks < 4; ks++)
        ldmx4(qf[ks], Q + SWZ((mrow + lrow) * 128 + ks * 32 + lcol));

    float oacc[8][4];
    #pragma unroll
    for (int i = 0; i < 8; i++)
        #pragma unroll
        for (int j = 0; j < 4; j++) oacc[i][j] = 0.f;
    float M0 = -1e30f, M1 = -1e30f, L0 = 0.f, L1 = 0.f;

    for (int i = 0; i < FA_NI; i++) {
        const uint32_t stb = ST0 + (i & 1) * STSZ;
        if (i > 0) { cp_wait(i + 1 < FA_NI ? 1 : 0); __syncthreads(); }

        float sacc[16][4];
        #pragma unroll
        for (int t = 0; t < 16; t++)
            #pragma unroll
            for (int j = 0; j < 4; j++) sacc[t][j] = 0.f;

        // S = Q K^T with B-fragment double buffering
        #pragma unroll
        for (int ks = 0; ks < 4; ks++) {
            uint32_t rb[2][4];
            ldmx4(rb[0], stb + SWZ(lrow * 128 + ks * 32 + lcol));
            #pragma unroll
            for (int ng = 0; ng < 8; ng++) {
                if (ng < 7)
                    ldmx4(rb[(ng + 1) & 1],
                          stb + SWZ(((ng + 1) * 16 + lrow) * 128 + ks * 32 + lcol));
                const uint32_t* rbc = rb[ng & 1];
                mma_f16(sacc[2 * ng],     qf[ks], rbc[0], rbc[2]);
                mma_f16(sacc[2 * ng + 1], qf[ks], rbc[1], rbc[3]);
            }
        }

        float mx0 = -1e30f, mx1 = -1e30f;
        #pragma unroll
        for (int t = 0; t < 16; t++) {
            sacc[t][0] *= 0.125f; sacc[t][1] *= 0.125f;
            sacc[t][2] *= 0.125f; sacc[t][3] *= 0.125f;
            mx0 = fmaxf(mx0, fmaxf(sacc[t][0], sacc[t][1]));
            mx1 = fmaxf(mx1, fmaxf(sacc[t][2], sacc[t][3]));
        }
        mx0 = fmaxf(mx0, __shfl_xor_sync(0xFFFFFFFFu, mx0, 1));
        mx0 = fmaxf(mx0, __shfl_xor_sync(0xFFFFFFFFu, mx0, 2));
        mx1 = fmaxf(mx1, __shfl_xor_sync(0xFFFFFFFFu, mx1, 1));
        mx1 = fmaxf(mx1, __shfl_xor_sync(0xFFFFFFFFu, mx1, 2));
        const float Mn0 = fmaxf(M0, mx0), Mn1 = fmaxf(M1, mx1);
        const float al0 = __expf(M0 - Mn0), al1 = __expf(M1 - Mn1);
        M0 = Mn0; M1 = Mn1;

        float s0 = 0.f, s1 = 0.f;
        #pragma unroll
        for (int t = 0; t < 16; t++) {
            sacc[t][0] = __expf(sacc[t][0] - M0); s0 += sacc[t][0];
            sacc[t][1] = __expf(sacc[t][1] - M0); s0 += sacc[t][1];
            sacc[t][2] = __expf(sacc[t][2] - M1); s1 += sacc[t][2];
            sacc[t][3] = __expf(sacc[t][3] - M1); s1 += sacc[t][3];
        }
        s0 += __shfl_xor_sync(0xFFFFFFFFu, s0, 1);
        s0 += __shfl_xor_sync(0xFFFFFFFFu, s0, 2);
        s1 += __shfl_xor_sync(0xFFFFFFFFu, s1, 1);
        s1 += __shfl_xor_sync(0xFFFFFFFFu, s1, 2);
        L0 = L0 * al0 + s0;
        L1 = L1 * al1 + s1;
        #pragma unroll
        for (int t = 0; t < 8; t++) {
            oacc[t][0] *= al0; oacc[t][1] *= al0;
            oacc[t][2] *= al1; oacc[t][3] *= al1;
        }

        const uint32_t vb = stb + 16384;
        #pragma unroll
        for (int ks = 0; ks < 8; ks++) {
            uint32_t ah[4];
            ah[0] = pack_f16x2(__float2half(sacc[2 * ks][0]),     __float2half(sacc[2 * ks][1]));
            ah[1] = pack_f16x2(__float2half(sacc[2 * ks][2]),     __float2half(sacc[2 * ks][3]));
            ah[2] = pack_f16x2(__float2half(sacc[2 * ks + 1][0]), __float2half(sacc[2 * ks + 1][1]));
            ah[3] = pack_f16x2(__float2half(sacc[2 * ks + 1][2]), __float2half(sacc[2 * ks + 1][3]));

            #pragma unroll
            for (int ng = 0; ng < 4; ng++) {
                uint32_t rb[4];
                ldmx4t(rb, vb + SWZ((ks * 16 + lrow) * 128 + ng * 32 + lcol));
                mma_f16(oacc[2 * ng],     ah, rb[0], rb[1]);
                mma_f16(oacc[2 * ng + 1], ah, rb[2], rb[3]);
            }
        }

        __syncthreads();
        if (i + 2 < FA_NI) loadkv(i & 1);
    }

    const float inv0 = 1.f / L0, inv1 = 1.f / L1;
    const int rq = lane >> 2, cq = (lane & 3) * 2;
    const long long base0 = (long long)b * SU_H + (long long)(q0 + mrow + rq) * HID + head * HDIM;
    const long long base1 = base0 + 8LL * HID;
    #pragma unroll
    for (int nt = 0; nt < 8; nt++) {
        const int cn = nt * 8 + cq;
        *(uint32_t*)(go + base0 + cn) =
            pack_f16x2(__float2half(oacc[nt][0] * inv0), __float2half(oacc[nt][1] * inv0));
        *(uint32_t*)(go + base1 + cn) =
            pack_f16x2(__float2half(oacc[nt][2] * inv1), __float2half(oacc[nt][3] * inv1));
    }
}

// ---------------- fused multi-buffer fp32->fp16 conversion ----------------
struct ConvJobs {
    const float* src[10];
    hf* dst[10];
    long long n4[10];
    int bstart[11];
};

__global__ __launch_bounds__(256) void conv_multi(ConvJobs J)
{
    int b = blockIdx.x;
    int j = 0;
    #pragma unroll
    for (int t = 0; t < 9; t++)
        if (b >= J.bstart[t + 1]) j = t + 1;
    long long i = (long long)(b - J.bstart[j]) * 256 + threadIdx.x;
    if (i >= J.n4[j]) return;
    float4 v = ((const float4*)J.src[j])[i];
    uint32_t* d = (uint32_t*)J.dst[j];
    d[i * 2]     = pack_f16x2(__float2half(v.x), __float2half(v.y));
    d[i * 2 + 1] = pack_f16x2(__float2half(v.z), __float2half(v.w));
}

// ---------------- transpose -> fp16 ----------------
__global__ __launch_bounds__(256) void transpose_h(
    const float* __restrict__ in, int ldi, long long sI1,
    hf* __restrict__ oh, int ldo, long long sO1)
{
    __shared__ float t[32][33];
    int z = blockIdx.z;
    in += (long long)z * sI1;
    long long oOff = (long long)z * sO1;
    int r0 = blockIdx.y * 32, c0 = blockIdx.x * 32;
    int tx = threadIdx.x & 31, ty8 = threadIdx.x >> 5;
    #pragma unroll
    for (int i = 0; i < 4; i++) {
        int ty = ty8 + i * 8;
        t[ty][tx] = in[(long long)(r0 + ty) * ldi + c0 + tx];
    }
    __syncthreads();
    #pragma unroll
    for (int i = 0; i < 4; i++) {
        int oy = ty8 + i * 8;
        long long idx = oOff + (long long)(c0 + oy) * ldo + r0 + tx;
        oh[idx] = __float2half(t[tx][oy]);
    }
}

// ---------------- rmsnorm -> fp32 + fp16 ----------------
__global__ __launch_bounds__(256) void rmsnorm_h(
    const float* __restrict__ x, const float* __restrict__ w,
    float* __restrict__ y, hf* __restrict__ yh)
{
    __shared__ float red[256];
    long long row = blockIdx.x;
    const float* xr = x + row * HID;
    int tid = threadIdx.x;
    float4 v0 = *(const float4*)(xr + tid * 4);
    float4 v1 = *(const float4*)(xr + 1024 + tid * 4);
    float s = v0.x * v0.x + v0.y * v0.y + v0.z * v0.z + v0.w * v0.w
            + v1.x * v1.x + v1.y * v1.y + v1.z * v1.z + v1.w * v1.w;
    red[tid] = s;
    __syncthreads();
    for (int st = 128; st > 0; st >>= 1) {
        if (tid < st) red[tid] += red[tid + st];
        __syncthreads();
    }
    float inv = rsqrtf(red[0] * (1.f / HID) + EPS_RMS);

    float4 w0 = *(const float4*)(w + tid * 4);
    float4 w1 = *(const float4*)(w + 1024 + tid * 4);
    float o[8];
    o[0] = v0.x * inv * w0.x; o[1] = v0.y * inv * w0.y;
    o[2] = v0.z * inv * w0.z; o[3] = v0.w * inv * w0.w;
    o[4] = v1.x * inv * w1.x; o[5] = v1.y * inv * w1.y;
    o[6] = v1.z * inv * w1.z; o[7] = v1.w * inv * w1.w;
    float* yr = y + row * HID;
    *(float4*)(yr + tid * 4) = make_float4(o[0], o[1], o[2], o[3]);
    *(float4*)(yr + 1024 + tid * 4) = make_float4(o[4], o[5], o[6], o[7]);
    hf* yhr = yh + row * HID;
    #pragma unroll
    for (int g = 0; g < 2; g++) {
        int off = g * 1024 + tid * 4;
        *(uint32_t*)(yhr + off) =
            pack_f16x2(__float2half(o[g * 4 + 0]), __float2half(o[g * 4 + 1]));
        *(uint32_t*)(yhr + off + 2) =
            pack_f16x2(__float2half(o[g * 4 + 2]), __float2half(o[g * 4 + 3]));
    }
}

// ---------------- host ----------------
static void* sym(const void* s) {
    void* p = nullptr;
    cudaGetSymbolAddress(&p, s);
    return p;
}

extern "C" void kernel_launch(void* const* d_in, const int* in_sizes, int n_in,
                              void* d_out, int out_size)
{
    const float* h_in = (const float*)d_in[0];
    const float* Wup  = (const float*)d_in[1];
    const float* bup  = (const float*)d_in[2];
    const float* anw  = (const float*)d_in[3];
    const float* Wq   = (const float*)d_in[4];
    const float* Wk   = (const float*)d_in[5];
    const float* Wv   = (const float*)d_in[6];
    const float* Wo   = (const float*)d_in[7];
    const float* mnw  = (const float*)d_in[8];
    const float* Wg   = (const float*)d_in[9];
    const float* Wu   = (const float*)d_in[10];
    const float* Wd   = (const float*)d_in[11];
    float* out = (float*)d_out;

    float* up_ = (float*)sym(g_up);
    float* x1_ = (float*)sym(g_x1);
    float* x2_ = (float*)sym(g_x2);
    float* x3_ = (float*)sym(g_x3);

    hf *cb  = (hf*)sym(f_c);
    hf *hth = (hf*)sym(f_ht);
    hf *wup = (hf*)sym(f_wup);
    hf *wqkv = (hf*)sym(f_wqkv);
    hf *wo = (hf*)sym(f_wo);
    hf *wg = (hf*)sym(f_wg);
    hf *wu = (hf*)sym(f_wu);
    hf *wd = (hf*)sym(f_wd);
    hf *x1h = (hf*)sym(f_x1);
    hf *x3h = (hf*)sym(f_x3);
    hf *qh = (hf*)sym(f_q);
    hf *kh = (hf*)sym(f_k);
    hf *vh = (hf*)sym(f_v);
    hf *oh = (hf*)sym(f_o);
    hf *gate16 = (hf*)sym(f_gate);
    hf *ubh = (hf*)sym(f_ub);

    const int SMEMG  = 1024 + 3 * 32768;            // 99328
    const int SMEMFA = 1024 + 16384 + 2 * 32768;    // 82944
    cudaFuncSetAttribute(mma_gemm, cudaFuncAttributeMaxDynamicSharedMemorySize, SMEMG);
    cudaFuncSetAttribute(flash_attn, cudaFuncAttributeMaxDynamicSharedMemorySize, SMEMFA);

    dim3 blk(256);
    dim3 blkG(128);

    const hf* nullh = nullptr;

    // 1) all fp32->fp16 conversions in one launch.
    {
        ConvJobs J;
        const float* srcs[10] = { h_in, h_in + S_H, Wup, Wq, Wk, Wv, Wo, Wg, Wu, Wd };
        hf* dsts[10] = { cb, cb + T_H, wup, wqkv, wqkv + W1N, wqkv + 2 * W1N, wo, wg, wu, wd };
        long long ns[10] = { S_H, S_H, WUPN, W1N, W1N, W1N, W1N, W2N, W2N, W2N };
        int cum = 0;
        for (int j = 0; j < 10; j++) {
            J.src[j] = srcs[j];
            J.dst[j] = dsts[j];
            J.n4[j] = ns[j] / 4;
            J.bstart[j] = cum;
            cum += (int)((J.n4[j] + 255) / 256);
        }
        J.bstart[10] = cum;
        conv_multi<<<cum, blk>>>(J);
    }

    // 2) h [S,H] -> hT [H,S] per batch
    transpose_h<<<dim3(HID / 32, S_LEN / 32, BATCH), blk>>>(
        h_in, HID, S_H, hth, S_LEN, S_H);

    // 3) up = Wup @ hT (+bias) -> fp32 (up_) + fp16 into f_c rows 512..
    mma_gemm<<<dim3(HID / 128, SU_LEN / 128, BATCH), blkG, SMEMG>>>(
        wup, S_LEN, 0,
        hth, S_LEN, S_H,
        up_, nullptr, HID, SU_H,
        bup, nullptr, 0, 0, nullh,
        cb + (long long)S_LEN * HID, T_H,
        cb + (long long)S_LEN * HID, T_H,
        S_LEN, 1.f);

    // 4) (k,v) all rows = [h;up] @ [Wk;Wv]^T  (segmented output, grid 768)
    mma_gemm<<<dim3(2 * HID / 128, T_LEN / 128, BATCH), blkG, SMEMG>>>(
        cb, HID, T_H,
        wqkv + W1N, HID, 0,
        nullptr, nullptr, HID, 0,
        nullptr, nullptr, 0, 0, nullh,
        kh, T_H, vh, T_H,
        HID, 1.f);

    // 5) x1 = rmsnorm(up)
    rmsnorm_h<<<BATCH * SU_LEN, blk>>>(up_, anw, x1_, x1h);

    // 6) q = x1 @ Wq^T
    mma_gemm<<<dim3(HID / 128, SU_LEN / 128, BATCH), blkG, SMEMG>>>(
        x1h, HID, SU_H,
        wqkv, HID, 0,
        nullptr, qh, HID, SU_H,
        nullptr, nullptr, 0, 0, nullh,
        nullptr, 0, nullptr, 0,
        HID, 1.f);

    // 7) fused flash attention -> o fp16
    flash_attn<<<dim3(SU_LEN / 128, BATCH * NHEAD), blk, SMEMFA>>>(
        qh, kh, vh, oh);

    // 8) x2 = o @ Wo^T + x1
    mma_gemm<<<dim3(HID / 128, SU_LEN / 128, BATCH), blkG, SMEMG>>>(
        oh, HID, SU_H,
        wo, HID, 0,
        x2_, nullptr, HID, SU_H,
        nullptr, x1_, HID, SU_H, nullh,
        nullptr, 0, nullptr, 0,
        HID, 1.f);

    // 9) x3 = rmsnorm(x2)
    rmsnorm_h<<<BATCH * SU_LEN, blk>>>(x2_, mnw, x3_, x3h);

    // 10) gate = x3 @ Wg^T -> fp16
    mma_gemm<<<dim3(INTER / 128, SU_LEN / 128, BATCH), blkG, SMEMG>>>(
        x3h, HID, SU_H,
        wg, HID, 0,
        nullptr, gate16, INTER, SU_I,
        nullptr, nullptr, 0, 0, nullh,
        nullptr, 0, nullptr, 0,
        HID, 1.f);

    // 11) ub = silu(gate) * (x3 @ Wu^T) -> fp16
    mma_gemm<<<dim3(INTER / 128, SU_LEN / 128, BATCH), blkG, SMEMG>>>(
        x3h, HID, SU_H,
        wu, HID, 0,
        nullptr, ubh, INTER, SU_I,
        nullptr, nullptr, 0, 0, gate16,
        nullptr, 0, nullptr, 0,
        HID, 1.f);

    // 12) out = ub @ Wd^T + x3
    mma_gemm<<<dim3(HID / 128, SU_LEN / 128, BATCH), blkG, SMEMG>>>(
        ubh, INTER, SU_I,
        wd, INTER, 0,
        out, nullptr, HID, SU_H,
        nullptr, x3_, HID, SU_H, nullh,
        nullptr, 0, nullptr, 0,
        INTER, 1.f);
}